// round 10
// baseline (speedup 1.0000x reference)
#include <cuda_runtime.h>
#include <cuda_bf16.h>
#include <cstdint>

// Output pattern, shape [2, G*N*N] flattened row-major, FLOAT32 values:
//   half 0: out[g*N*N + i]     = float(i / N)   (row index)
//   half 1: out[H + g*N*N + i] = float(i % N)   (col index),  H = G*N*N
// Pure write-only stream (512 MiB for N=4096, G=4); inputs' values unused.
//
// Final shape (validated R3-R9):
//  - (R4) per-STG warp footprint = contiguous fully-covered 2KB span
//    (thread = one float4); wider per-thread tiling triggers L2/HBM RMW (2x).
//  - (R8) persistent grid regresses (serialized units lower store pressure).
//  - (R5-R9) HBM write-stream ceiling ~7.45 TB/s, ~84% DRAM active; 2KB-grain
//    L2 hash neutralizes locality tricks beyond the 2KB warp span.
//  - This round: 1024-thread blocks, ZERO loop — block covers its whole 16KB
//    row in one STG.128 per thread; minimal ALU, immediate store issue.

// Fast path: N % 1024 == 0 after /4 => N % 4096 == 0... use N % (T*4) == 0
// with T chosen at launch. Kernel assumes blockDim.x * 4 == N exactly when
// ITERS==1; general loop retained for other multiples.
__global__ void fa_row_split_kernel(float* __restrict__ out,
                                    unsigned N, unsigned G,
                                    long long halfElems) {
    const unsigned r = blockIdx.y;
    const unsigned z = blockIdx.z;
    const bool colHalf = (z >= G);
    const unsigned g = colHalf ? (z - G) : z;
    const long long NNll = (long long)N * (long long)N;

    const unsigned t4 = threadIdx.x * 4u;
    long long base = (colHalf ? halfElems : 0LL)
                   + (long long)g * NNll
                   + (long long)r * (long long)N
                   + (long long)t4;

    const unsigned stride = blockDim.x * 4u;
    const unsigned iters = N / stride;            // ==1 when blockDim*4 == N

    if (colHalf) {
        float c = (float)t4;
        for (unsigned j = 0; j < iters; j++) {
            __stcs(reinterpret_cast<float4*>(out + base),
                   make_float4(c, c + 1.0f, c + 2.0f, c + 3.0f));
            base += stride;
            c += (float)stride;
        }
    } else {
        const float rf = (float)r;
        const float4 rv = make_float4(rf, rf, rf, rf);
        for (unsigned j = 0; j < iters; j++) {
            __stcs(reinterpret_cast<float4*>(out + base), rv);
            base += stride;
        }
    }
}

// Generic path: thread = one float4 per half, N % 4 == 0.
__global__ void fa_vec_kernel(float* __restrict__ out,
                              unsigned N, unsigned NN, long long halfElems) {
    unsigned i4 = ((unsigned)blockIdx.x * blockDim.x + threadIdx.x) * 4u;
    if (i4 >= NN) return;
    unsigned r = i4 / N;
    unsigned c = i4 - r * N;
    long long base = (long long)blockIdx.y * (long long)NN + (long long)i4;
    float rf = (float)r, cf = (float)c;
    __stcs(reinterpret_cast<float4*>(out + base),
           make_float4(rf, rf, rf, rf));
    __stcs(reinterpret_cast<float4*>(out + halfElems + base),
           make_float4(cf, cf + 1.0f, cf + 2.0f, cf + 3.0f));
}

// Scalar fallback.
__global__ void fa_scalar_kernel(float* __restrict__ out,
                                 unsigned N, unsigned NN, long long halfElems) {
    unsigned i = (unsigned)blockIdx.x * blockDim.x + threadIdx.x;
    if (i >= NN) return;
    unsigned r = i / N;
    unsigned c = i - r * N;
    long long base = (long long)blockIdx.y * (long long)NN + (long long)i;
    out[base] = (float)r;
    out[halfElems + base] = (float)c;
}

extern "C" void kernel_launch(void* const* d_in, const int* in_sizes, int n_in,
                              void* d_out, int out_size) {
    (void)d_in;
    // Derive N: the input size s with out_size == 2*G*s*s, integer 1<=G<=4096.
    long long N = 0, G = 0;
    for (int i = 0; i < n_in; i++) {
        long long s = (long long)in_sizes[i];
        if (s <= 0) continue;
        long long denom = 2LL * s * s;
        if (denom <= 0) continue;
        if ((long long)out_size % denom != 0) continue;
        long long g = (long long)out_size / denom;
        if (g >= 1 && g <= 4096) { N = s; G = g; break; }
    }
    if (N == 0) {
        N = (long long)in_sizes[2];
        long long denom = 2LL * N * N;
        G = (denom > 0 && (long long)out_size % denom == 0)
                ? (long long)out_size / denom : 1;
    }

    const long long NNll = N * N;
    const unsigned NN = (unsigned)NNll;
    const long long halfElems = G * NNll;
    float* out = (float*)d_out;

    if ((N % 4096) == 0 && N <= 65535LL && 2 * G <= 65535LL) {
        // Loop-free: 1024 threads x float4 == 4096 floats == one row chunk.
        // (For N > 4096 the kernel's iters loop covers the remainder.)
        dim3 grid(1, (unsigned)N, (unsigned)(2 * G));
        fa_row_split_kernel<<<grid, 1024>>>(out, (unsigned)N, (unsigned)G,
                                            halfElems);
    } else if ((N % 1024) == 0 && N <= 65535LL && 2 * G <= 65535LL) {
        dim3 grid(1, (unsigned)N, (unsigned)(2 * G));
        fa_row_split_kernel<<<grid, 256>>>(out, (unsigned)N, (unsigned)G,
                                           halfElems);
    } else if ((N % 4) == 0 && NNll <= 0xFFFFFFFFLL) {
        const int threads = 256;
        const unsigned elems4 = NN / 4u;
        unsigned gx = (elems4 + threads - 1) / threads;
        if (gx == 0) gx = 1;
        dim3 grid(gx, (unsigned)G, 1);
        fa_vec_kernel<<<grid, threads>>>(out, (unsigned)N, NN, halfElems);
    } else {
        const int threads = 256;
        unsigned gx = (unsigned)((NNll + threads - 1) / threads);
        if (gx == 0) gx = 1;
        dim3 grid(gx, (unsigned)G, 1);
        fa_scalar_kernel<<<grid, threads>>>(out, (unsigned)N, NN, halfElems);
    }
}

// round 11
// speedup vs baseline: 1.1687x; 1.1687x over previous
#include <cuda_runtime.h>
#include <cuda_bf16.h>
#include <cstdint>

// Output pattern, shape [2, G*N*N] flattened row-major, FLOAT32 values:
//   half 0: out[g*N*N + i]     = float(i / N)   (row index)
//   half 1: out[H + g*N*N + i] = float(i % N)   (col index),  H = G*N*N
// Pure write-only stream (512 MiB for N=4096, G=4); inputs' values unused.
//
// FINAL version — the measured optimum across R3-R10:
//  - (R4)  per-instruction warp footprint must be a contiguous fully-covered
//          2KB span (thread = one float4); wider per-thread contiguous tiling
//          fractures 128B lines -> L2/HBM read-modify-write (2x time).
//  - (R8)  persistent grid regresses: serialized per-block units present less
//          outstanding-store pressure than fresh small CTAs (+9%).
//  - (R10) one-shot stores (1024 threads, no loop) regress: the 64-bit index
//          prologue is amortized over only 16B/thread -> ALU/issue-bound
//          (ALU 47%, DRAM 66%) (+22%).
//  - (R5-R9) HBM write-stream ceiling ~7.45 TB/s achieved (~84% DRAM active);
//          the 2KB-grain L2 address hash neutralizes locality tricks beyond
//          the 2KB warp span.
//  - __stcs (evict-first): output is 4x L2 capacity and never re-read.
//
// Shape: 256-thread blocks, grid (1, N, 2G); z<G writes the row-half, z>=G
// the col-half. Each block emits ONE 16KB row as a pure sequential stream,
// 4 loop iterations of one STG.128 per thread (64B/thread amortizes the
// prologue; loop body is STG + IADD only).

__global__ void fa_row_split_kernel(float* __restrict__ out,
                                    unsigned N, unsigned G,
                                    long long halfElems) {
    const unsigned r = blockIdx.y;                 // row index
    const unsigned z = blockIdx.z;
    const bool colHalf = (z >= G);
    const unsigned g = colHalf ? (z - G) : z;
    const long long NNll = (long long)N * (long long)N;

    long long base = (colHalf ? halfElems : 0LL)
                   + (long long)g * NNll
                   + (long long)r * (long long)N
                   + (long long)(threadIdx.x * 4u);

    const unsigned stride = blockDim.x * 4u;       // 1024 floats
    const unsigned iters = N / stride;             // 4 for N=4096, 256 thr

    if (colHalf) {
        float c = (float)(threadIdx.x * 4u);
        for (unsigned j = 0; j < iters; j++) {
            __stcs(reinterpret_cast<float4*>(out + base),
                   make_float4(c, c + 1.0f, c + 2.0f, c + 3.0f));
            base += stride;
            c += (float)stride;
        }
    } else {
        const float rf = (float)r;
        const float4 rv = make_float4(rf, rf, rf, rf);
        for (unsigned j = 0; j < iters; j++) {
            __stcs(reinterpret_cast<float4*>(out + base), rv);
            base += stride;
        }
    }
}

// Generic path: thread = one float4 per half, N % 4 == 0.
__global__ void fa_vec_kernel(float* __restrict__ out,
                              unsigned N, unsigned NN, long long halfElems) {
    unsigned i4 = ((unsigned)blockIdx.x * blockDim.x + threadIdx.x) * 4u;
    if (i4 >= NN) return;
    unsigned r = i4 / N;
    unsigned c = i4 - r * N;
    long long base = (long long)blockIdx.y * (long long)NN + (long long)i4;
    float rf = (float)r, cf = (float)c;
    __stcs(reinterpret_cast<float4*>(out + base),
           make_float4(rf, rf, rf, rf));
    __stcs(reinterpret_cast<float4*>(out + halfElems + base),
           make_float4(cf, cf + 1.0f, cf + 2.0f, cf + 3.0f));
}

// Scalar fallback.
__global__ void fa_scalar_kernel(float* __restrict__ out,
                                 unsigned N, unsigned NN, long long halfElems) {
    unsigned i = (unsigned)blockIdx.x * blockDim.x + threadIdx.x;
    if (i >= NN) return;
    unsigned r = i / N;
    unsigned c = i - r * N;
    long long base = (long long)blockIdx.y * (long long)NN + (long long)i;
    out[base] = (float)r;
    out[halfElems + base] = (float)c;
}

extern "C" void kernel_launch(void* const* d_in, const int* in_sizes, int n_in,
                              void* d_out, int out_size) {
    (void)d_in;
    // Derive N: the input size s with out_size == 2*G*s*s, integer 1<=G<=4096.
    long long N = 0, G = 0;
    for (int i = 0; i < n_in; i++) {
        long long s = (long long)in_sizes[i];
        if (s <= 0) continue;
        long long denom = 2LL * s * s;
        if (denom <= 0) continue;
        if ((long long)out_size % denom != 0) continue;
        long long g = (long long)out_size / denom;
        if (g >= 1 && g <= 4096) { N = s; G = g; break; }
    }
    if (N == 0) {
        N = (long long)in_sizes[2];
        long long denom = 2LL * N * N;
        G = (denom > 0 && (long long)out_size % denom == 0)
                ? (long long)out_size / denom : 1;
    }

    const long long NNll = N * N;
    const unsigned NN = (unsigned)NNll;
    const long long halfElems = G * NNll;
    float* out = (float*)d_out;
    const int threads = 256;

    if ((N % (threads * 4)) == 0 && N <= 65535LL && 2 * G <= 65535LL) {
        dim3 grid(1, (unsigned)N, (unsigned)(2 * G));
        fa_row_split_kernel<<<grid, threads>>>(out, (unsigned)N, (unsigned)G,
                                               halfElems);
    } else if ((N % 4) == 0 && NNll <= 0xFFFFFFFFLL) {
        const unsigned elems4 = NN / 4u;
        unsigned gx = (elems4 + threads - 1) / threads;
        if (gx == 0) gx = 1;
        dim3 grid(gx, (unsigned)G, 1);
        fa_vec_kernel<<<grid, threads>>>(out, (unsigned)N, NN, halfElems);
    } else {
        unsigned gx = (unsigned)((NNll + threads - 1) / threads);
        if (gx == 0) gx = 1;
        dim3 grid(gx, (unsigned)G, 1);
        fa_scalar_kernel<<<grid, threads>>>(out, (unsigned)N, NN, halfElems);
    }
}